// round 14
// baseline (speedup 1.0000x reference)
#include <cuda_runtime.h>
#include <math_constants.h>

// Problem constants (fixed shapes from setup_inputs)
#define BB   8      // batch
#define NPTS 256    // N = 4096/16
#define BETA 192    // 0.75*N
#define KN   768    // 3*N oversampled points
#define CO   128    // out channels
#define HO   256
#define WO   256
#define CF   64     // res2 channels
#define HF   512
#define WF   512
#define CFEAT (CO + CF)   // 192
#define RPTS 16           // points per render block

__device__ float g_unc[BB * KN];
__device__ __align__(16) float g_featC[BB * KN * CO];   // cached coarse features
__device__ int   g_idx[BB * BETA];                      // selected oversample idx

#define PACK_F32X2(out, lo, hi) \
    asm("mov.b64 %0, {%1, %2};" : "=l"(out) : "f"(lo), "f"(hi))
#define FFMA2(acc, a, b) \
    asm("fma.rn.f32x2 %0, %1, %2, %0;" : "+l"(acc) : "l"(a), "l"(b))

// select element d (0..3) of a float4
__device__ __forceinline__ float pick4(float4 q, int d) {
    float v = (d == 1) ? q.y : q.x;
    v = (d == 2) ? q.z : v;
    v = (d == 3) ? q.w : v;
    return v;
}

// merge running top2 (m1>=m2) with single value v
__device__ __forceinline__ void merge1(float &m1, float &m2, float v) {
    float n1 = fmaxf(m1, v);
    m2 = fmaxf(fminf(m1, v), m2);
    m1 = n1;
}
// merge running top2 with another pair (o1>=o2)
__device__ __forceinline__ void merge2(float &m1, float &m2, float o1, float o2) {
    float n1 = fmaxf(m1, o1);
    float n2 = fmaxf(fminf(m1, o1), fmaxf(m2, o2));
    m1 = n1; m2 = n2;
}

// ---------------------------------------------------------------------------
// Kernel 1: per-point uncertainty + coarse-feature cache.
// 2 warps per point (one per bilinear row); block = 4 points (256 thr).
// ---------------------------------------------------------------------------
__global__ void uncert_kernel(const float* __restrict__ outm,
                              const float* __restrict__ rand_over) {
    __shared__ float part[4][2];
    __shared__ float rv[4][2][CO];    // per-point, per-row channel blends (4 KB)
    int tid = threadIdx.x;
    int wrp = tid >> 5;
    int lane = tid & 31;
    int ptl = wrp >> 1;          // local point 0..3
    int r   = wrp & 1;           // bilinear row 0/1
    int idx = blockIdx.x * 4 + ptl;   // global b*KN + p
    int b = idx / KN;

    float px = rand_over[idx * 2 + 0];
    float py = rand_over[idx * 2 + 1];
    float gx = px * (float)WO - 0.5f;
    float gy = py * (float)HO - 0.5f;
    float x0f = floorf(gx), y0f = floorf(gy);
    float wx = gx - x0f, wy = gy - y0f;
    int x0 = (int)x0f, y0 = (int)y0f;

    const float* base = outm + (long long)b * CO * HO * WO;
    bool xv0 = (x0 >= 0) && (x0 < WO);
    bool xv1 = (x0 + 1 >= 0) && (x0 + 1 < WO);
    int xc0 = min(max(x0, 0), WO - 1);
    int xc1 = min(max(x0 + 1, 0), WO - 1);

    int y = y0 + r;
    bool yv = (y >= 0) && (y < HO);
    int yc = min(max(y, 0), HO - 1);
    const float* rp = base + yc * WO;
    float wyr = r ? wy : (1.f - wy);

    // 8 scalar loads, batched for MLP
    float v0[4], v1[4];
#pragma unroll
    for (int cc = 0; cc < 4; cc++) {
        long long co = (long long)(lane + cc * 32) * (HO * WO);
        v0[cc] = __ldg(rp + co + xc0);
        v1[cc] = __ldg(rp + co + xc1);
    }

    // per-channel x-blend (cached for render's coarse gather)
    float m0 = (yv && xv0) ? 1.f : 0.f;
    float m1 = (yv && xv1) ? 1.f : 0.f;
#pragma unroll
    for (int cc = 0; cc < 4; cc++) {
        rv[ptl][r][lane + cc * 32] =
            wyr * ((1.f - wx) * m0 * v0[cc] + wx * m1 * v1[cc]);
    }

    float a1 = -CUDART_INF_F, a2 = -CUDART_INF_F;   // corner x0
    float b1 = -CUDART_INF_F, b2 = -CUDART_INF_F;   // corner x0+1
#pragma unroll
    for (int cc = 0; cc < 4; cc++) {
        merge1(a1, a2, v0[cc]);
        merge1(b1, b2, v1[cc]);
    }
#pragma unroll
    for (int off = 16; off; off >>= 1) {
        merge2(a1, a2, __shfl_xor_sync(0xFFFFFFFFu, a1, off),
                       __shfl_xor_sync(0xFFFFFFFFu, a2, off));
        merge2(b1, b2, __shfl_xor_sync(0xFFFFFFFFu, b1, off),
                       __shfl_xor_sync(0xFFFFFFFFu, b2, off));
    }
    float e0 = (yv && xv0) ? (a2 - a1) : 0.f;   // -(top1 - top2), zero padded
    float e1 = (yv && xv1) ? (b2 - b1) : 0.f;
    if (lane == 0)
        part[ptl][r] = wyr * ((1.f - wx) * e0 + wx * e1);
    __syncthreads();

    if (r == 0 && lane == 0)
        g_unc[idx] = part[ptl][0] + part[ptl][1];

    // write cached coarse features: 4 pts x 128 ch, 2 entries per thread
#pragma unroll
    for (int it = 0; it < 2; it++) {
        int s = tid + it * 256;
        int pt = s >> 7;
        int c  = s & 127;
        g_featC[(long long)(blockIdx.x * 4 + pt) * CO + c] =
            rv[pt][0][c] + rv[pt][1][c];
    }
}

// ---------------------------------------------------------------------------
// Kernel 2: exact top-192 per batch; register-resident bitonic, shfl stages.
// ---------------------------------------------------------------------------
__global__ void topk_kernel(const float* __restrict__ rand_over,
                            const float* __restrict__ rand_cov,
                            float* __restrict__ points) {
    int b = blockIdx.x;
    int t = threadIdx.x;
    __shared__ unsigned long long sk[1024];

    unsigned long long key = 0ull;  // pad: sorts last (real keys have high word > 0)
    if (t < KN) {
        float u = g_unc[b * KN + t];
        unsigned ub = __float_as_uint(u);
        ub = (ub & 0x80000000u) ? ~ub : (ub | 0x80000000u);  // total order
        key = ((unsigned long long)ub << 32) | (unsigned long long)(0xFFFFFFFFu - (unsigned)t);
    }

    for (int k = 2; k <= 1024; k <<= 1) {
        for (int j = k >> 1; j; j >>= 1) {
            unsigned long long other;
            if (j >= 32) {
                __syncthreads();
                sk[t] = key;
                __syncthreads();
                other = sk[t ^ j];
            } else {
                other = __shfl_xor_sync(0xFFFFFFFFu, key, j);
            }
            bool iLower = ((t & j) == 0);
            bool desc   = ((t & k) == 0);
            unsigned long long mx = (key > other) ? key : other;
            unsigned long long mn = (key > other) ? other : key;
            key = (desc == iLower) ? mx : mn;   // overall descending
        }
    }

    if (t < BETA) {
        unsigned idx = 0xFFFFFFFFu - (unsigned)(key & 0xFFFFFFFFull);
        g_idx[b * BETA + t] = (int)idx;
        points[(b * NPTS + t) * 2 + 0] = rand_over[(b * KN + idx) * 2 + 0];
        points[(b * NPTS + t) * 2 + 1] = rand_over[(b * KN + idx) * 2 + 1];
    } else if (t < NPTS) {
        int i = t - BETA;
        points[(b * NPTS + t) * 2 + 0] = rand_cov[(b * (NPTS - BETA) + i) * 2 + 0];
        points[(b * NPTS + t) * 2 + 1] = rand_cov[(b * (NPTS - BETA) + i) * 2 + 1];
    }
}

// ---------------------------------------------------------------------------
// Kernel 3 (fused render): gather 16 points x 192 ch into fs, then GEMM with
// smem-staged weight (two 96-k chunks). 128 blocks x 1024 threads.
// ---------------------------------------------------------------------------
__device__ __forceinline__ float bilerp_sample(const float* __restrict__ base,
                                               int H, int W, float px, float py) {
    float gx = px * (float)W - 0.5f;
    float gy = py * (float)H - 0.5f;
    float x0f = floorf(gx), y0f = floorf(gy);
    float wx = gx - x0f, wy = gy - y0f;
    int x0 = (int)x0f, y0 = (int)y0f;
    bool xv0 = (x0 >= 0) && (x0 < W);
    bool xv1 = (x0 + 1 >= 0) && (x0 + 1 < W);
    bool yv0 = (y0 >= 0) && (y0 < H);
    bool yv1 = (y0 + 1 >= 0) && (y0 + 1 < H);
    int xc0 = min(max(x0, 0), W - 1);
    int xc1 = min(max(x0 + 1, 0), W - 1);
    int yc0 = min(max(y0, 0), H - 1);
    int yc1 = min(max(y0 + 1, 0), H - 1);

    int bx = xc0 & ~3;          // aligned float4 window (bx <= W-4 always)
    int d0 = xc0 - bx;
    int d1 = xc1 - bx;          // 0..4
    const float* r0 = base + yc0 * W;
    const float* r1 = base + yc1 * W;
    float4 qa = __ldg(reinterpret_cast<const float4*>(r0 + bx));
    float4 qb = __ldg(reinterpret_cast<const float4*>(r1 + bx));
    float v00 = pick4(qa, d0);
    float v10 = pick4(qb, d0);
    float v01, v11;
    if (d1 == 4) {              // per-thread rare (~12%) overflow case
        v01 = __ldg(r0 + xc1);
        v11 = __ldg(r1 + xc1);
    } else {
        v01 = pick4(qa, d1);
        v11 = pick4(qb, d1);
    }
    v00 = (yv0 && xv0) ? v00 : 0.f;
    v01 = (yv0 && xv1) ? v01 : 0.f;
    v10 = (yv1 && xv0) ? v10 : 0.f;
    v11 = (yv1 && xv1) ? v11 : 0.f;
    return v00 * (1.f - wx) * (1.f - wy) + v01 * wx * (1.f - wy)
         + v10 * (1.f - wx) * wy + v11 * wx * wy;
}

__global__ __launch_bounds__(1024) void render_kernel(
        const float* __restrict__ outm,
        const float* __restrict__ res2,
        const float* __restrict__ weight,
        const float* __restrict__ bias,
        const float* __restrict__ points,
        float* __restrict__ rend) {
    __shared__ float ws[CO][97];                    // one 96-k chunk, 49.7 KB
    __shared__ __align__(8) float fs[CFEAT][RPTS];  // 12 KB

    int blk = blockIdx.x;
    int b  = blk / (NPTS / RPTS);
    int n0 = (blk % (NPTS / RPTS)) * RPTS;
    int t = threadIdx.x;

    // ---- phase 1: gather 16*192 = 3072 samples, 3 per thread
#pragma unroll
    for (int it = 0; it < 3; it++) {
        int s = t + it * 1024;
        int p = s / CFEAT;
        int k = s - p * CFEAT;
        int n = n0 + p;
        float v;
        if (k < CO) {
            if (n < BETA) {
                // importance point: cached bilinear coarse feature
                int gi = g_idx[b * BETA + n];
                v = __ldg(g_featC + (long long)(b * KN + gi) * CO + k);
            } else {
                float px = points[(b * NPTS + n) * 2 + 0];
                float py = points[(b * NPTS + n) * 2 + 1];
                v = bilerp_sample(outm + ((long long)(b * CO + k)) * (HO * WO),
                                  HO, WO, px, py);
            }
        } else {
            float px = points[(b * NPTS + n) * 2 + 0];
            float py = points[(b * NPTS + n) * 2 + 1];
            v = bilerp_sample(res2 + ((long long)(b * CF + (k - CO))) * (HF * WF),
                              HF, WF, px, py);
        }
        fs[k][p] = v;
    }

    // ---- phase 2: GEMM, two 96-k chunks of smem-staged weight
    int o = t & 127;          // out channel
    int g = t >> 7;           // n-pair: (2g, 2g+1); warp-uniform
    unsigned long long acc = 0ull;

#pragma unroll
    for (int h = 0; h < 2; h++) {
        __syncthreads();
        // stage ws[row][0..95] = weight[row][h*96 .. +95]; 3 float4 per thread
#pragma unroll
        for (int j = t; j < CO * 24; j += 1024) {
            int row = j / 24, part = j % 24;
            float4 w4 = __ldg(reinterpret_cast<const float4*>(
                weight + row * CFEAT + h * 96 + part * 4));
            ws[row][part * 4 + 0] = w4.x;
            ws[row][part * 4 + 1] = w4.y;
            ws[row][part * 4 + 2] = w4.z;
            ws[row][part * 4 + 3] = w4.w;
        }
        __syncthreads();

#pragma unroll 8
        for (int j = 0; j < 96; j++) {
            int k = h * 96 + j;
            float wv = ws[o][j];                     // conflict-free (pad 97)
            unsigned long long wp;
            PACK_F32X2(wp, wv, wv);
            unsigned long long fpair =
                *reinterpret_cast<const unsigned long long*>(&fs[k][2 * g]);  // broadcast
            FFMA2(acc, wp, fpair);
        }
    }

    float bv = bias[o];
    float2 outv;
    outv.x = __uint_as_float((unsigned)(acc & 0xFFFFFFFFull)) + bv;
    outv.y = __uint_as_float((unsigned)(acc >> 32)) + bv;
    *reinterpret_cast<float2*>(rend + ((long long)b * CO + o) * NPTS + n0 + 2 * g) = outv;
}

// ---------------------------------------------------------------------------
// Launch
// ---------------------------------------------------------------------------
extern "C" void kernel_launch(void* const* d_in, const int* in_sizes, int n_in,
                              void* d_out, int out_size) {
    // metadata order: x, res2, out, rand_over, rand_cov, weight, bias
    const float* res2      = (const float*)d_in[1];
    const float* outm      = (const float*)d_in[2];
    const float* rand_over = (const float*)d_in[3];
    const float* rand_cov  = (const float*)d_in[4];
    const float* weight    = (const float*)d_in[5];
    const float* bias      = (const float*)d_in[6];

    float* rend   = (float*)d_out;                       // [B,128,256]
    float* points = (float*)d_out + BB * CO * NPTS;      // [B,256,2]

    // 2 warps per point (row-split), 4 points per 256-thread block
    uncert_kernel<<<(BB * KN) / 4, 256>>>(outm, rand_over);
    topk_kernel<<<BB, 1024>>>(rand_over, rand_cov, points);
    render_kernel<<<BB * (NPTS / RPTS), 1024>>>(outm, res2, weight, bias, points, rend);
}